// round 8
// baseline (speedup 1.0000x reference)
#include <cuda_runtime.h>

// Problem constants (fixed by the dataset)
#define B   4
#define P   12000
#define NF  64
#define XS  512
#define YS  512
#define CELLS    (XS * YS)                // 262144 per batch
#define BP_TOTAL (B * P)                  // 48000
#define SPANS    256                      // 1024-cell spans per batch
#define LIST_MAX 128                      // >> mean 23.4 touched/span

// Epoch machinery: effective epoch e = g_epoch + 1, in [1, 32767] (never 0,
// so CUDA's load-time zero-init of all state parses as "stale/empty").
//   g_slot value = (e << 17) | (bp + 1)   [bp+1 <= 48000 < 2^17]
//   g_cnt  value = (e << 16) | count
// The LAST fused block to finish bumps g_epoch for the next call -> no
// reset kernel, no 4 MB clears, fully graph-replay-safe.
__device__ unsigned g_epoch;                      // stored value, e = this + 1
__device__ unsigned g_done;                       // finish ticket counter
__device__ unsigned g_slot[B * CELLS];            // 4 MB
__device__ int      g_next[BP_TOTAL];             // chain next, -1 terminated
__device__ unsigned g_cnt[B * SPANS];             // epoch-tagged span counters
__device__ int      g_list[B * SPANS * LIST_MAX]; // touched cell ids (512 KB)

// ---------------------------------------------------------------------------
// K1: build per-cell chains + per-span touched lists.
// Slot claim via atomicExch; span counter via lock-free CAS (handles the
// stale-tag -> (e<<16)|1 transition without any clearing pass).
// ---------------------------------------------------------------------------
__global__ void claim_kernel(const int* __restrict__ coord,
                             const int* __restrict__ contains) {
    unsigned bp = blockIdx.x * blockDim.x + threadIdx.x;
    if (bp >= BP_TOTAL) return;
    if (contains[bp] != 1) return;

    const unsigned e = g_epoch + 1u;             // uniform broadcast load
    const unsigned b = bp / P;
    const int y = coord[bp * 3 + 1];
    const int x = coord[bp * 3 + 2];
    const unsigned cell = (unsigned)(y * XS + x);

    unsigned old = atomicExch(&g_slot[b * CELLS + cell], (e << 17) | (bp + 1u));
    bool fresh = (old >> 17) == e;               // cell already claimed this call?
    g_next[bp] = fresh ? (int)(old & 0x1FFFFu) - 1 : -1;

    if (!fresh) {                                // first claimant: register cell
        unsigned span = b * SPANS + (cell >> 10);
        unsigned cur = g_cnt[span];
        for (;;) {
            unsigned want, pos;
            if ((cur >> 16) == e) { want = cur + 1u;        pos = cur & 0xFFFFu; }
            else                  { want = (e << 16) | 1u;  pos = 0u; }
            unsigned prev = atomicCAS(&g_cnt[span], cur, want);
            if (prev == cur) {
                if (pos < LIST_MAX)
                    g_list[span * LIST_MAX + pos] = (int)cell;
                break;
            }
            cur = prev;                          // someone else advanced; retry
        }
    }
}

// ---------------------------------------------------------------------------
// K2: zero + fixup, linear geometry (block id order == address order).
// Block = one 4 KB chunk: blk -> (b, f, span), span fastest.
//   - broadcast-load epoch + span count, prefetch <=64 list entries
//     (all hidden under the store stream; P(n>64) ~ 1e-13)
//   - one linear float4 zero store per thread
//   - __syncthreads, then n threads resolve their cell: slot head ->
//     chain walk over pillars[p*64+f] -> 4B overwrite on a just-written line.
//   - last block to finish bumps the epoch and rearms the ticket counter.
// ---------------------------------------------------------------------------
__global__ void fused_kernel(const float* __restrict__ pillars,
                             float* __restrict__ out) {
    const unsigned blk  = blockIdx.x;            // 0..65535
    const unsigned tid  = threadIdx.x;           // 0..255
    const unsigned b    = blk >> 14;
    const unsigned f    = (blk >> 8) & 63;
    const unsigned span = blk & 255;
    const unsigned sp   = b * SPANS + span;

    // Early independent loads (retire under the store stream)
    const unsigned e = g_epoch + 1u;
    const unsigned cw = g_cnt[sp];
    const unsigned n = ((cw >> 16) == e) ? (cw & 0xFFFFu) : 0u;
    int cell = (tid < 64) ? g_list[sp * LIST_MAX + tid] : 0;

    // Linear zero store: one float4 per thread, block = contiguous 4 KB
    ((float4*)out)[(blk << 8) + tid] = make_float4(0.f, 0.f, 0.f, 0.f);

    __syncthreads();   // order zero-stores before fixup overwrites

    if (tid < n && tid < LIST_MAX) {
        if (tid >= 64) cell = g_list[sp * LIST_MAX + tid];   // ~never taken
        unsigned head = g_slot[b * CELLS + (unsigned)cell];  // fresh this call
        int p = (int)(head & 0x1FFFFu) - 1;
        float acc = 0.f;
        while (p >= 0) {                                     // chain length ~1
            acc += pillars[(unsigned)p * NF + f];
            p = g_next[p];
        }
        out[((b * NF + f) << 18) + (unsigned)cell] = acc;
    }

    // Epoch bump by the last block to finish (exactly one per call)
    if (tid == 0) {
        unsigned t = atomicAdd(&g_done, 1u);
        if (t == gridDim.x - 1u) {
            g_done = 0u;
            g_epoch = e % 32767u;   // next call's e = this+1 in [1,32767]
        }
    }
}

extern "C" void kernel_launch(void* const* d_in, const int* in_sizes, int n_in,
                              void* d_out, int out_size) {
    const float* pillars  = (const float*)d_in[0];  // [B, P, NF] fp32
    const int*   coord    = (const int*)  d_in[1];  // [B, P, 3]  int32
    const int*   contains = (const int*)  d_in[2];  // [B, P]     int32
    float*       out      = (float*)d_out;          // [B, NF, XS, YS] fp32

    claim_kernel<<<(BP_TOTAL + 255) / 256, 256>>>(coord, contains);
    fused_kernel<<<B * NF * SPANS, 256>>>(pillars, out);   // 65536 blocks
}

// round 10
// speedup vs baseline: 1.7555x; 1.7555x over previous
#include <cuda_runtime.h>

// Problem constants (fixed by the dataset)
#define B   4
#define P   12000
#define NF  64
#define XS  512
#define YS  512
#define CELLS    (XS * YS)                // 262144 per batch
#define BP_TOTAL (B * P)                  // 48000
#define SPANS    256                      // 1024-cell spans per batch
#define LIST_MAX 128                      // >> mean 23.4 touched/span

// Epoch-tagged slot map: value = (epoch<<17) | (bp+1); epoch in [1,32767].
// Entries written in a previous call parse as empty -> no 4 MB init needed.
__device__ unsigned g_epoch;                      // current tag (0 at load)
__device__ unsigned g_slot[B * CELLS];            // 4 MB
__device__ int      g_next[BP_TOTAL];             // chain next, -1 terminated
__device__ unsigned g_cnt[B * SPANS];             // touched cells per span
__device__ int      g_list[B * SPANS * LIST_MAX]; // touched cell ids (512 KB)

// ---------------------------------------------------------------------------
// K0: bump epoch + clear span counters. One block (pure launch-latency cost).
// ---------------------------------------------------------------------------
__global__ void reset_kernel() {
    if (threadIdx.x == 0) g_epoch = g_epoch % 32767u + 1u;  // 1..32767, never 0
    g_cnt[threadIdx.x] = 0;                                  // 1024 counters
}

// ---------------------------------------------------------------------------
// K1: build per-cell chains + per-span touched lists (round-7 proven form:
// atomicExch on slots, plain atomicAdd on pre-cleared counters).
// ---------------------------------------------------------------------------
__global__ void claim_kernel(const int* __restrict__ coord,
                             const int* __restrict__ contains) {
    unsigned bp = blockIdx.x * blockDim.x + threadIdx.x;
    if (bp >= BP_TOTAL) return;
    if (contains[bp] != 1) return;

    const unsigned e = g_epoch;                  // uniform broadcast load
    const unsigned b = bp / P;
    const int y = coord[bp * 3 + 1];
    const int x = coord[bp * 3 + 2];
    const unsigned cell = (unsigned)(y * XS + x);

    unsigned old = atomicExch(&g_slot[b * CELLS + cell], (e << 17) | (bp + 1u));
    bool fresh = (old >> 17) == e;               // cell already claimed this call?
    g_next[bp] = fresh ? (int)(old & 0x1FFFFu) - 1 : -1;

    if (!fresh) {                                // first claimant: register cell
        unsigned span = b * SPANS + (cell >> 10);
        unsigned pos = atomicAdd(&g_cnt[span], 1u);
        if (pos < LIST_MAX)
            g_list[span * LIST_MAX + pos] = (int)cell;
    }
}

// ---------------------------------------------------------------------------
// K2: zero + fixup, linear geometry, 16 KB chunks.
// Block = (b, f, chunk) with chunk fastest => block id order == address
// order. Chunk = 4096 cells = 4 spans at one plane.
//   - tid<4 loads the 4 span counts into smem; every thread prefetches one
//     list entry (span tid>>6, slot tid&63) — all hidden by the stores
//   - 4 strided float4 zero stores per thread (4-deep store MLP)
//   - __syncthreads, then ~94 threads resolve their cell: slot head ->
//     chain walk over pillars[p*64+f] -> 4B overwrite on a just-written line
// ---------------------------------------------------------------------------
__global__ void fused_kernel(const float* __restrict__ pillars,
                             float* __restrict__ out) {
    __shared__ unsigned s_n[4];

    const unsigned blk   = blockIdx.x;           // 0..16383
    const unsigned tid   = threadIdx.x;          // 0..255
    const unsigned b     = blk >> 12;
    const unsigned f     = (blk >> 6) & 63;
    const unsigned chunk = blk & 63;             // 64 chunks per plane
    const unsigned sp0   = b * SPANS + (chunk << 2);   // first of 4 spans

    // Early independent loads (retire under the store stream)
    const unsigned e = g_epoch;
    if (tid < 4) {
        unsigned cw = g_cnt[sp0 + tid];
        s_n[tid] = cw;                           // raw count (cleared each call)
    }
    const unsigned s = tid >> 6;                 // span within chunk (0..3)
    const unsigned j = tid & 63;                 // list slot (0..63)
    int cell = g_list[(sp0 + s) * LIST_MAX + j]; // prefetch (may be stale/unused)

    // Linear zero stores: 4 strided float4 per thread = contiguous 16 KB/block
    float4* base = (float4*)out + (blk << 10);
    const float4 z = make_float4(0.f, 0.f, 0.f, 0.f);
    base[tid      ] = z;
    base[tid + 256] = z;
    base[tid + 512] = z;
    base[tid + 768] = z;

    __syncthreads();   // counts visible + zero-stores ordered before fixups

    const unsigned n = s_n[s];
    if (j < n) {
        unsigned head = g_slot[b * CELLS + (unsigned)cell];  // fresh this call
        int p = (int)(head & 0x1FFFFu) - 1;
        float acc = 0.f;
        while (p >= 0) {                                     // chain length ~1
            acc += pillars[(unsigned)p * NF + f];
            p = g_next[p];
        }
        out[((b * NF + f) << 18) + (unsigned)cell] = acc;
    }
    // Overflow (>64 touched in one span): essentially never (P ~ 1e-13)
    for (unsigned jj = j + 64; jj < n && jj < LIST_MAX; jj += 64) {
        int c2 = g_list[(sp0 + s) * LIST_MAX + jj];
        unsigned head = g_slot[b * CELLS + (unsigned)c2];
        int p = (int)(head & 0x1FFFFu) - 1;
        float acc = 0.f;
        while (p >= 0) {
            acc += pillars[(unsigned)p * NF + f];
            p = g_next[p];
        }
        out[((b * NF + f) << 18) + (unsigned)c2] = acc;
    }
    (void)e;
}

extern "C" void kernel_launch(void* const* d_in, const int* in_sizes, int n_in,
                              void* d_out, int out_size) {
    const float* pillars  = (const float*)d_in[0];  // [B, P, NF] fp32
    const int*   coord    = (const int*)  d_in[1];  // [B, P, 3]  int32
    const int*   contains = (const int*)  d_in[2];  // [B, P]     int32
    float*       out      = (float*)d_out;          // [B, NF, XS, YS] fp32

    reset_kernel<<<1, B * SPANS>>>();                            // 1024 threads
    claim_kernel<<<(BP_TOTAL + 255) / 256, 256>>>(coord, contains);
    fused_kernel<<<B * NF * 64, 256>>>(pillars, out);            // 16384 blocks
}